// round 15
// baseline (speedup 1.0000x reference)
#include <cuda_runtime.h>
#include <cuda_fp16.h>
#include <cstdint>

#define B_ 2
#define T_ 192
#define C_ 512
#define H_ 8
#define D_ 64
#define PROJC (5 * C_)  // 2560
#define NITEMS ((B_ * H_) * (T_ / 8))   // 384 work items
#define NCTA 296                        // 2 CTAs x 148 SMs

__device__ float g_proj[B_ * T_ * PROJC];
__device__ float g_attn[B_ * T_ * C_];
__device__ int   g_ctr;

// ---------------- helpers ----------------
__device__ __forceinline__ void mma16816(float* c, const unsigned* a,
                                         unsigned b0, unsigned b1) {
    asm volatile(
        "mma.sync.aligned.m16n8k16.row.col.f32.f16.f16.f32 "
        "{%0,%1,%2,%3},{%4,%5,%6,%7},{%8,%9},{%0,%1,%2,%3};\n"
        : "+f"(c[0]), "+f"(c[1]), "+f"(c[2]), "+f"(c[3])
        : "r"(a[0]), "r"(a[1]), "r"(a[2]), "r"(a[3]), "r"(b0), "r"(b1));
}
__device__ __forceinline__ unsigned packh2(float lo, float hi) {
    __half2 h = __floats2half2_rn(lo, hi);
    return *(unsigned*)&h;
}
__device__ __forceinline__ unsigned hmul2u(unsigned a, unsigned b) {
    __half2 r = __hmul2(*(__half2*)&a, *(__half2*)&b);
    return *(unsigned*)&r;
}
__device__ __forceinline__ float ex2(float x) {
    float r; asm("ex2.approx.ftz.f32 %0, %1;" : "=f"(r) : "f"(x)); return r;
}

// ---------------------------------------------------------------------------
// fp16 GEMM + bias (fp32 accum): 64x64 tile, 4 warps, K-step 32, double-buffer.
// Block (0,0) optionally resets the attention work counter (rst != nullptr).
// ---------------------------------------------------------------------------
#define HA_STR 20
#define HB_STR 72
#define HAS (64 * HA_STR)
#define HBS (16 * HB_STR)
#define HSTG (HAS + HBS)

__global__ __launch_bounds__(128) void gemm_h16_kernel(
    const float* __restrict__ A, const float* __restrict__ Bm,
    const float* __restrict__ bias, float* __restrict__ C,
    int M, int N, int K, int* rst)
{
    __shared__ unsigned smh[2 * HSTG];

    if (rst && threadIdx.x == 0 && blockIdx.x == 0 && blockIdx.y == 0)
        *rst = 0;

    const int t = threadIdx.x, lane = t & 31, w = t >> 5;
    const int grp = lane >> 2, tid4 = lane & 3;
    const int wm = w & 1, wn = w >> 1;
    const int row0 = blockIdx.y * 64, col0 = blockIdx.x * 64;

    const int ar = t >> 1, acb = (t & 1) << 4;
    const int br = t >> 4, bc = (t & 15) << 2;

    float4 a0, a1, a2, a3, b0, b1, b2, b3;
    #define LDT(kt) do { \
        a0 = *(const float4*)&A[(size_t)(row0 + ar) * K + (kt) + acb]; \
        a1 = *(const float4*)&A[(size_t)(row0 + ar) * K + (kt) + acb + 4]; \
        a2 = *(const float4*)&A[(size_t)(row0 + ar) * K + (kt) + acb + 8]; \
        a3 = *(const float4*)&A[(size_t)(row0 + ar) * K + (kt) + acb + 12]; \
        b0 = *(const float4*)&Bm[(size_t)((kt) + 2 * br)      * N + col0 + bc]; \
        b1 = *(const float4*)&Bm[(size_t)((kt) + 2 * br + 1)  * N + col0 + bc]; \
        b2 = *(const float4*)&Bm[(size_t)((kt) + 2 * br + 16) * N + col0 + bc]; \
        b3 = *(const float4*)&Bm[(size_t)((kt) + 2 * br + 17) * N + col0 + bc]; \
    } while (0)
    #define STT(S) do { \
        unsigned* Ah = (S); unsigned* Bh = (S) + HAS; \
        int aw = ar * HA_STR + (acb >> 1); \
        Ah[aw + 0] = packh2(a0.x, a0.y); Ah[aw + 1] = packh2(a0.z, a0.w); \
        Ah[aw + 2] = packh2(a1.x, a1.y); Ah[aw + 3] = packh2(a1.z, a1.w); \
        Ah[aw + 4] = packh2(a2.x, a2.y); Ah[aw + 5] = packh2(a2.z, a2.w); \
        Ah[aw + 6] = packh2(a3.x, a3.y); Ah[aw + 7] = packh2(a3.z, a3.w); \
        int bw = br * HB_STR + bc; \
        Bh[bw + 0] = packh2(b0.x, b1.x); Bh[bw + 1] = packh2(b0.y, b1.y); \
        Bh[bw + 2] = packh2(b0.z, b1.z); Bh[bw + 3] = packh2(b0.w, b1.w); \
        int bw2 = (br + 8) * HB_STR + bc; \
        Bh[bw2 + 0] = packh2(b2.x, b3.x); Bh[bw2 + 1] = packh2(b2.y, b3.y); \
        Bh[bw2 + 2] = packh2(b2.z, b3.z); Bh[bw2 + 3] = packh2(b2.w, b3.w); \
    } while (0)

    const int niter = K >> 5;
    LDT(0);
    STT(smh);
    if (niter > 1) LDT(32);
    __syncthreads();

    float c[2][4][4] = {};

    for (int it = 0; it < niter; it++) {
        unsigned* S = smh + (it & 1) * HSTG;
        unsigned* Ah = S;
        unsigned* Bh = S + HAS;

        #pragma unroll
        for (int kc = 0; kc < 2; kc++) {
            const int k8 = kc << 3;
            unsigned a[2][4];
            #pragma unroll
            for (int mt = 0; mt < 2; mt++) {
                int r = (wm << 5) + (mt << 4) + grp;
                a[mt][0] = Ah[r * HA_STR + k8 + tid4];
                a[mt][1] = Ah[(r + 8) * HA_STR + k8 + tid4];
                a[mt][2] = Ah[r * HA_STR + k8 + 4 + tid4];
                a[mt][3] = Ah[(r + 8) * HA_STR + k8 + 4 + tid4];
            }
            #pragma unroll
            for (int n = 0; n < 4; n++) {
                int cc = (wn << 5) + (n << 3) + grp;
                unsigned bb0 = Bh[(k8 + tid4) * HB_STR + cc];
                unsigned bb1 = Bh[(k8 + 4 + tid4) * HB_STR + cc];
                mma16816(c[0][n], a[0], bb0, bb1);
                mma16816(c[1][n], a[1], bb0, bb1);
            }
        }

        if (it + 1 < niter) {
            unsigned* Sn = smh + ((it + 1) & 1) * HSTG;
            STT(Sn);
            if (it + 2 < niter) LDT((it + 2) << 5);
            __syncthreads();
        }
    }

    #pragma unroll
    for (int mt = 0; mt < 2; mt++)
        #pragma unroll
        for (int n = 0; n < 4; n++) {
            int row = row0 + (wm << 5) + (mt << 4) + grp;
            int col = col0 + (wn << 5) + (n << 3) + (tid4 << 1);
            float2 bv = *(const float2*)&bias[col];
            *(float2*)&C[(size_t)row * N + col] =
                make_float2(c[mt][n][0] + bv.x, c[mt][n][1] + bv.y);
            *(float2*)&C[(size_t)(row + 8) * N + col] =
                make_float2(c[mt][n][2] + bv.x, c[mt][n][3] + bv.y);
        }
    #undef LDT
    #undef STT
}

// ---------------------------------------------------------------------------
// Fused two-simplicial attention: R11/R14 math per item, persistent CTAs
// pulling items (bh-major) from a global atomic counter. K2h/V2h init is
// skipped when the item's (b,h) matches the previous item's.
// ---------------------------------------------------------------------------
#define QSC 0.18033688011112042f
#define FMC 5.770780163555854f

#define OFF_Q    0
#define OFF_V1   512
#define OFF_ACC  1536
#define OFF_RZ   2048
#define OFF_K1H  2080
#define OFF_K2H  2656
#define OFF_V2H  9568
#define OFF_UH   16480
#define SMEM_FLOATS 25696  // 102,784 B

__global__ __launch_bounds__(256, 2) void attn_kernel(
    const float* __restrict__ proj, float* __restrict__ outp, int* ctr)
{
    extern __shared__ float sm[];
    __shared__ int s_item;
    float* Qs   = sm + OFF_Q;
    float* V1s  = sm + OFF_V1;
    float* accS = sm + OFF_ACC;
    float* redZ = sm + OFF_RZ;
    unsigned* K1h = (unsigned*)(sm + OFF_K1H);
    unsigned* K2h = (unsigned*)(sm + OFF_K2H);
    unsigned* V2h = (unsigned*)(sm + OFF_V2H);
    unsigned* Uh  = (unsigned*)(sm + OFF_UH);

    const int t = threadIdx.x, lane = t & 31, w = t >> 5;
    const int grp = lane >> 2, tid4 = lane & 3;
    const int wm = w & 1;
    const int wn = w >> 1;

    const int ttp = t & 127;
    const int jjp = ttp >> 4;
    const int d4p = (ttp & 15) << 2;
    const bool isK1 = (t < 128);

    int prev_bh = -1;

    while (true) {
        if (t == 0) s_item = atomicAdd(ctr, 1);
        __syncthreads();
        const int item = s_item;
        if (item >= NITEMS) break;

        const int bh = item / (T_ / 8);
        const int i0 = (item % (T_ / 8)) << 3;
        const int b = bh >> 3, h = bh & 7;
        const float* base = proj + (size_t)b * T_ * PROJC + h * D_;
        const float* pfbase = base + (size_t)jjp * PROJC +
                              (isK1 ? C_ : 2 * C_) + d4p;

        // ---- per-item init ----
        float4 preg = *(const float4*)pfbase;
        for (int idx = t; idx < 512; idx += 256) {
            int r = idx >> 6, d = idx & 63;
            Qs[idx]   = base[(size_t)(i0 + r) * PROJC + d] * QSC;
            accS[idx] = 0.f;
        }
        if (t < 32) redZ[t] = 0.f;
        if (bh != prev_bh) {
            for (int idx = t; idx < 192 * 32; idx += 256) {
                int k = idx >> 5, p = idx & 31;
                float2 v = *(const float2*)&base[(size_t)k * PROJC + 3 * C_ + 2 * p];
                K2h[k * 36 + p] = packh2(v.x, v.y);
            }
            for (int idx = t; idx < 96 * 64; idx += 256) {
                int pr = idx >> 6, d = idx & 63;
                float lo = base[(size_t)(2 * pr)     * PROJC + 4 * C_ + d];
                float hi = base[(size_t)(2 * pr + 1) * PROJC + 4 * C_ + d];
                V2h[pr * 72 + d] = packh2(lo, hi);
            }
        }
        __syncthreads();

        // ---- pin Q fragments in registers ----
        unsigned Qreg[32];
        #pragma unroll
        for (int rp = 0; rp < 4; rp++) {
            int i = (wm << 2) + rp;
            #pragma unroll
            for (int u = 0; u < 8; u++) {
                int kk = u >> 1;
                int d0 = (kk << 4) + (tid4 << 1) + ((u & 1) << 3);
                Qreg[rp * 8 + u] = packh2(Qs[(i << 6) + d0], Qs[(i << 6) + d0 + 1]);
            }
        }

        // ---- commit tile 0 (buf 0), prefetch tile 1 ----
        if (isK1) {
            uint2 kw;
            kw.x = packh2(preg.x, preg.y);
            kw.y = packh2(preg.z, preg.w);
            *(uint2*)&K1h[jjp * 36 + (d4p >> 1)] = kw;
        } else {
            *(float4*)&V1s[(jjp << 6) + d4p] = preg;
        }
        preg = *(const float4*)(pfbase + (size_t)8 * PROJC);
        __syncthreads();

        for (int n_t = 0; n_t < 24; n_t++) {
            const int buf = n_t & 1;
            const unsigned* K1b = K1h + buf * 288 + grp * 36;

            // ---- GEMM1 ----
            float c1[2][6][4] = {};
            #pragma unroll
            for (int kk = 0; kk < 4; kk++) {
                unsigned k1a  = K1b[(kk << 3) + tid4];
                unsigned k1b_ = K1b[(kk << 3) + 4 + tid4];
                unsigned A[2][4];
                #pragma unroll
                for (int a = 0; a < 2; a++) {
                    A[a][0] = hmul2u(Qreg[(a << 4) + (kk << 1)],     k1a);
                    A[a][1] = hmul2u(Qreg[(a << 4) + 8 + (kk << 1)], k1a);
                    A[a][2] = hmul2u(Qreg[(a << 4) + (kk << 1) + 1],     k1b_);
                    A[a][3] = hmul2u(Qreg[(a << 4) + 8 + (kk << 1) + 1], k1b_);
                }
                #pragma unroll
                for (int n = 0; n < 6; n++) {
                    int row = wn * 48 + (n << 3) + grp;
                    unsigned b0 = K2h[row * 36 + (kk << 3) + tid4];
                    unsigned b1 = K2h[row * 36 + (kk << 3) + 4 + tid4];
                    mma16816(c1[0][n], A[0], b0, b1);
                    mma16816(c1[1][n], A[1], b0, b1);
                }
            }

            // ---- fixed-max softmax ----
            unsigned ea[2][3][4];
            float zs[4] = {0.f, 0.f, 0.f, 0.f};
            #pragma unroll
            for (int a = 0; a < 2; a++)
                #pragma unroll
                for (int n = 0; n < 6; n++) {
                    float e0 = ex2(c1[a][n][0] - FMC);
                    float e1 = ex2(c1[a][n][1] - FMC);
                    float e2 = ex2(c1[a][n][2] - FMC);
                    float e3 = ex2(c1[a][n][3] - FMC);
                    zs[2*a+0] += e0 + e1;
                    zs[2*a+1] += e2 + e3;
                    unsigned p0 = packh2(e0, e1);
                    unsigned p1 = packh2(e2, e3);
                    if (n & 1) { ea[a][n >> 1][2] = p0; ea[a][n >> 1][3] = p1; }
                    else       { ea[a][n >> 1][0] = p0; ea[a][n >> 1][1] = p1; }
                }

            // ---- GEMM2 partial U ----
            #pragma unroll
            for (int nh = 0; nh < 2; nh++) {
                float u[2][4][4] = {};
                #pragma unroll
                for (int kk2 = 0; kk2 < 3; kk2++) {
                    int rb = 24 * wn + (kk2 << 3);
                    #pragma unroll
                    for (int n = 0; n < 4; n++) {
                        int nn = (nh << 2) + n;
                        unsigned b0 = V2h[(rb + tid4) * 72 + (nn << 3) + grp];
                        unsigned b1 = V2h[(rb + 4 + tid4) * 72 + (nn << 3) + grp];
                        mma16816(u[0][n], ea[0][kk2], b0, b1);
                        mma16816(u[1][n], ea[1][kk2], b0, b1);
                    }
                }
                unsigned* Uq = Uh + wn * 2304;
                #pragma unroll
                for (int a = 0; a < 2; a++)
                    #pragma unroll
                    for (int n = 0; n < 4; n++) {
                        int nn = (nh << 2) + n;
                        int r  = (wm << 5) + (a << 4) + grp;
                        int cw = (nn << 2) + tid4;
                        Uq[r * 36 + cw]       = packh2(u[a][n][0], u[a][n][1]);
                        Uq[(r + 8) * 36 + cw] = packh2(u[a][n][2], u[a][n][3]);
                    }
            }

            // ---- commit K1/V1 for tile n+1; prefetch n+2 ----
            if (n_t + 1 < 24) {
                if (isK1) {
                    uint2 kw;
                    kw.x = packh2(preg.x, preg.y);
                    kw.y = packh2(preg.z, preg.w);
                    *(uint2*)&K1h[(buf ^ 1) * 288 + jjp * 36 + (d4p >> 1)] = kw;
                } else {
                    *(float4*)&V1s[((buf ^ 1) << 9) + (jjp << 6) + d4p] = preg;
                }
                if (n_t + 2 < 24)
                    preg = *(const float4*)(pfbase +
                            (size_t)((n_t + 2) << 3) * PROJC);
            }
            __syncthreads();   // sync_B

            // ---- epilogue ----
            {
                #pragma unroll
                for (int s = 0; s < 4; s++)
                    #pragma unroll
                    for (int off = 16; off > 0; off >>= 1)
                        zs[s] += __shfl_xor_sync(0xffffffffu, zs[s], off);
                if (lane == 0) {
                    #pragma unroll
                    for (int s = 0; s < 4; s++)
                        redZ[(wn << 3) + (wm << 2) + s] += zs[s];
                }
                const int i = t >> 5;
                const float* V1b = V1s + (buf << 9);
                float2 acc = *(float2*)&accS[(i << 6) + (lane << 1)];
                #pragma unroll
                for (int jj = 0; jj < 8; jj++) {
                    int m = (i << 3) + jj;
                    float sx = 0.f, sy = 0.f;
                    #pragma unroll
                    for (int q = 0; q < 4; q++) {
                        unsigned uw = Uh[q * 2304 + m * 36 + lane];
                        float2 f = __half22float2(*(__half2*)&uw);
                        sx += f.x; sy += f.y;
                    }
                    float2 v1 = *(const float2*)&V1b[(jj << 6) + (lane << 1)];
                    acc.x += v1.x * sx;
                    acc.y += v1.y * sy;
                }
                *(float2*)&accS[(i << 6) + (lane << 1)] = acc;
            }
            __syncthreads();   // sync_E
        }

        // ---- finalize this item ----
        {
            const int i = t >> 5;
            float Z = redZ[i] + redZ[8 + i] + redZ[16 + i] + redZ[24 + i];
            float invZ = 1.0f / Z;
            float2 acc = *(float2*)&accS[(i << 6) + (lane << 1)];
            acc.x *= invZ; acc.y *= invZ;
            *(float2*)&outp[(size_t)(b * T_ + i0 + i) * C_ + h * D_ +
                            (lane << 1)] = acc;
        }
        prev_bh = bh;
    }
}

// ---------------------------------------------------------------------------
extern "C" void kernel_launch(void* const* d_in, const int* in_sizes, int n_in,
                              void* d_out, int out_size)
{
    const float* x     = (const float*)d_in[0];
    const float* W_in  = (const float*)d_in[1];
    const float* b_in  = (const float*)d_in[2];
    const float* W_out = (const float*)d_in[3];
    const float* b_out = (const float*)d_in[4];
    float* y = (float*)d_out;

    float *proj, *attn;
    int* ctr;
    cudaGetSymbolAddress((void**)&proj, g_proj);
    cudaGetSymbolAddress((void**)&attn, g_attn);
    cudaGetSymbolAddress((void**)&ctr, g_ctr);

    const size_t SMEM = (size_t)SMEM_FLOATS * sizeof(float);   // 102,784 B
    cudaFuncSetAttribute(attn_kernel,
                         cudaFuncAttributeMaxDynamicSharedMemorySize, (int)SMEM);

    // 1) proj = x @ W_in + b_in (block (0,0) resets the work counter)
    dim3 g1(PROJC / 64, (B_ * T_) / 64);
    gemm_h16_kernel<<<g1, 128>>>(x, W_in, b_in, proj, B_ * T_, PROJC, C_, ctr);

    // 2) fused attention: persistent CTAs + work stealing
    attn_kernel<<<NCTA, 256, SMEM>>>(proj, attn, ctr);

    // 3) y = attn @ W_out + b_out
    dim3 g2(C_ / 64, (B_ * T_) / 64);
    gemm_h16_kernel<<<g2, 128>>>(attn, W_out, b_out, y, B_ * T_, C_, C_,
                                 nullptr);
}

// round 16
// speedup vs baseline: 1.0290x; 1.0290x over previous
#include <cuda_runtime.h>
#include <cuda_fp16.h>
#include <cstdint>

#define B_ 2
#define T_ 192
#define C_ 512
#define H_ 8
#define D_ 64
#define PROJC (5 * C_)  // 2560
#define NCTA 296
#define NU (16 * 24 * 24)       // 9216 units (bh x itile x jtile)
#define UBASE (NU / NCTA)       // 31
#define UREM  (NU % NCTA)       // 40

__device__ float g_proj[B_ * T_ * PROJC];
__device__ float g_accp[B_ * T_ * C_];
__device__ float g_z[B_ * H_ * T_];

// ---------------- helpers ----------------
__device__ __forceinline__ void mma16816(float* c, const unsigned* a,
                                         unsigned b0, unsigned b1) {
    asm volatile(
        "mma.sync.aligned.m16n8k16.row.col.f32.f16.f16.f32 "
        "{%0,%1,%2,%3},{%4,%5,%6,%7},{%8,%9},{%0,%1,%2,%3};\n"
        : "+f"(c[0]), "+f"(c[1]), "+f"(c[2]), "+f"(c[3])
        : "r"(a[0]), "r"(a[1]), "r"(a[2]), "r"(a[3]), "r"(b0), "r"(b1));
}
__device__ __forceinline__ unsigned packh2(float lo, float hi) {
    __half2 h = __floats2half2_rn(lo, hi);
    return *(unsigned*)&h;
}
__device__ __forceinline__ unsigned hmul2u(unsigned a, unsigned b) {
    __half2 r = __hmul2(*(__half2*)&a, *(__half2*)&b);
    return *(unsigned*)&r;
}
__device__ __forceinline__ float ex2(float x) {
    float r; asm("ex2.approx.ftz.f32 %0, %1;" : "=f"(r) : "f"(x)); return r;
}

// ---------------------------------------------------------------------------
// fp16 GEMM + bias (fp32 accum): 64x64 tile, 4 warps, K-step 32, double-buffer.
// zp   != null : scale A[row][col] by 1/zp[(b*H+h)*T+t]  (out-GEMM normalize)
// zacc != null : zero zacc (B*T*C) and zz (B*H*T) first   (proj prologue)
// ---------------------------------------------------------------------------
#define HA_STR 20
#define HB_STR 72
#define HAS (64 * HA_STR)
#define HBS (16 * HB_STR)
#define HSTG (HAS + HBS)

__global__ __launch_bounds__(128) void gemm_h16_kernel(
    const float* __restrict__ A, const float* __restrict__ Bm,
    const float* __restrict__ bias, float* __restrict__ C,
    int M, int N, int K,
    const float* __restrict__ zp, float* zacc, float* zz)
{
    __shared__ unsigned smh[2 * HSTG];

    const int t = threadIdx.x, lane = t & 31, w = t >> 5;
    const int grp = lane >> 2, tid4 = lane & 3;
    const int wm = w & 1, wn = w >> 1;
    const int row0 = blockIdx.y * 64, col0 = blockIdx.x * 64;

    if (zacc) {
        int gtid = (blockIdx.y * gridDim.x + blockIdx.x) * 128 + t;
        int nthr = gridDim.x * gridDim.y * 128;
        for (int idx = gtid; idx < B_ * T_ * C_; idx += nthr) zacc[idx] = 0.f;
        for (int idx = gtid; idx < B_ * H_ * T_; idx += nthr) zz[idx] = 0.f;
    }

    const int ar = t >> 1, acb = (t & 1) << 4;
    const int br = t >> 4, bc = (t & 15) << 2;

    float4 a0, a1, a2, a3, b0, b1, b2, b3;
    #define LDT(kt) do { \
        a0 = *(const float4*)&A[(size_t)(row0 + ar) * K + (kt) + acb]; \
        a1 = *(const float4*)&A[(size_t)(row0 + ar) * K + (kt) + acb + 4]; \
        a2 = *(const float4*)&A[(size_t)(row0 + ar) * K + (kt) + acb + 8]; \
        a3 = *(const float4*)&A[(size_t)(row0 + ar) * K + (kt) + acb + 12]; \
        if (zp) { \
            int rr = row0 + ar; int bb = rr / T_, tt = rr - bb * T_; \
            int hh = ((kt) + acb) >> 6; \
            float zi = 1.0f / zp[(bb * H_ + hh) * T_ + tt]; \
            a0.x *= zi; a0.y *= zi; a0.z *= zi; a0.w *= zi; \
            a1.x *= zi; a1.y *= zi; a1.z *= zi; a1.w *= zi; \
            a2.x *= zi; a2.y *= zi; a2.z *= zi; a2.w *= zi; \
            a3.x *= zi; a3.y *= zi; a3.z *= zi; a3.w *= zi; \
        } \
        b0 = *(const float4*)&Bm[(size_t)((kt) + 2 * br)      * N + col0 + bc]; \
        b1 = *(const float4*)&Bm[(size_t)((kt) + 2 * br + 1)  * N + col0 + bc]; \
        b2 = *(const float4*)&Bm[(size_t)((kt) + 2 * br + 16) * N + col0 + bc]; \
        b3 = *(const float4*)&Bm[(size_t)((kt) + 2 * br + 17) * N + col0 + bc]; \
    } while (0)
    #define STT(S) do { \
        unsigned* Ah = (S); unsigned* Bh = (S) + HAS; \
        int aw = ar * HA_STR + (acb >> 1); \
        Ah[aw + 0] = packh2(a0.x, a0.y); Ah[aw + 1] = packh2(a0.z, a0.w); \
        Ah[aw + 2] = packh2(a1.x, a1.y); Ah[aw + 3] = packh2(a1.z, a1.w); \
        Ah[aw + 4] = packh2(a2.x, a2.y); Ah[aw + 5] = packh2(a2.z, a2.w); \
        Ah[aw + 6] = packh2(a3.x, a3.y); Ah[aw + 7] = packh2(a3.z, a3.w); \
        int bw = br * HB_STR + bc; \
        Bh[bw + 0] = packh2(b0.x, b1.x); Bh[bw + 1] = packh2(b0.y, b1.y); \
        Bh[bw + 2] = packh2(b0.z, b1.z); Bh[bw + 3] = packh2(b0.w, b1.w); \
        int bw2 = (br + 8) * HB_STR + bc; \
        Bh[bw2 + 0] = packh2(b2.x, b3.x); Bh[bw2 + 1] = packh2(b2.y, b3.y); \
        Bh[bw2 + 2] = packh2(b2.z, b3.z); Bh[bw2 + 3] = packh2(b2.w, b3.w); \
    } while (0)

    const int niter = K >> 5;
    LDT(0);
    STT(smh);
    if (niter > 1) LDT(32);
    __syncthreads();

    float c[2][4][4] = {};

    for (int it = 0; it < niter; it++) {
        unsigned* S = smh + (it & 1) * HSTG;
        unsigned* Ah = S;
        unsigned* Bh = S + HAS;

        #pragma unroll
        for (int kc = 0; kc < 2; kc++) {
            const int k8 = kc << 3;
            unsigned a[2][4];
            #pragma unroll
            for (int mt = 0; mt < 2; mt++) {
                int r = (wm << 5) + (mt << 4) + grp;
                a[mt][0] = Ah[r * HA_STR + k8 + tid4];
                a[mt][1] = Ah[(r + 8) * HA_STR + k8 + tid4];
                a[mt][2] = Ah[r * HA_STR + k8 + 4 + tid4];
                a[mt][3] = Ah[(r + 8) * HA_STR + k8 + 4 + tid4];
            }
            #pragma unroll
            for (int n = 0; n < 4; n++) {
                int cc = (wn << 5) + (n << 3) + grp;
                unsigned bb0 = Bh[(k8 + tid4) * HB_STR + cc];
                unsigned bb1 = Bh[(k8 + 4 + tid4) * HB_STR + cc];
                mma16816(c[0][n], a[0], bb0, bb1);
                mma16816(c[1][n], a[1], bb0, bb1);
            }
        }

        if (it + 1 < niter) {
            unsigned* Sn = smh + ((it + 1) & 1) * HSTG;
            STT(Sn);
            if (it + 2 < niter) LDT((it + 2) << 5);
            __syncthreads();
        }
    }

    #pragma unroll
    for (int mt = 0; mt < 2; mt++)
        #pragma unroll
        for (int n = 0; n < 4; n++) {
            int row = row0 + (wm << 5) + (mt << 4) + grp;
            int col = col0 + (wn << 5) + (n << 3) + (tid4 << 1);
            float2 bv = *(const float2*)&bias[col];
            *(float2*)&C[(size_t)row * N + col] =
                make_float2(c[mt][n][0] + bv.x, c[mt][n][1] + bv.y);
            *(float2*)&C[(size_t)(row + 8) * N + col] =
                make_float2(c[mt][n][2] + bv.x, c[mt][n][3] + bv.y);
        }
    #undef LDT
    #undef STT
}

// ---------------------------------------------------------------------------
// Fused two-simplicial attention: persistent CTAs, static contiguous unit
// ranges (unit = one j-tile of one (bh,i-tile) item). Partials atomicAdd'ed
// into accp/z; normalization deferred to the out-GEMM.
// ---------------------------------------------------------------------------
#define QSC 0.18033688011112042f
#define FMC 5.770780163555854f

#define OFF_Q    0
#define OFF_V1   512
#define OFF_ACC  1536
#define OFF_RZ   2048
#define OFF_K1H  2080
#define OFF_K2H  2656
#define OFF_V2H  9568
#define OFF_UH   16480
#define SMEM_FLOATS 25696  // 102,784 B

__global__ __launch_bounds__(256, 2) void attn_kernel(
    const float* __restrict__ proj, float* __restrict__ accp,
    float* __restrict__ zp)
{
    extern __shared__ float sm[];
    float* Qs   = sm + OFF_Q;
    float* V1s  = sm + OFF_V1;
    float* accS = sm + OFF_ACC;
    float* redZ = sm + OFF_RZ;
    unsigned* K1h = (unsigned*)(sm + OFF_K1H);
    unsigned* K2h = (unsigned*)(sm + OFF_K2H);
    unsigned* V2h = (unsigned*)(sm + OFF_V2H);
    unsigned* Uh  = (unsigned*)(sm + OFF_UH);

    const int t = threadIdx.x, lane = t & 31, w = t >> 5;
    const int grp = lane >> 2, tid4 = lane & 3;
    const int wm = w & 1;
    const int wn = w >> 1;

    const int ttp = t & 127;
    const int jjp = ttp >> 4;
    const int d4p = (ttp & 15) << 2;
    const bool isK1 = (t < 128);

    const int cid = blockIdx.x;
    int u   = UBASE * cid + (cid < UREM ? cid : UREM);
    int end = u + UBASE + (cid < UREM ? 1 : 0);

    int cur_bh = -1;

    while (u < end) {
        const int item = u / 24;
        const int jt0  = u - item * 24;
        const int bh   = item / 24;
        const int i0   = (item - bh * 24) << 3;
        const int run  = min(24 - jt0, end - u);
        const int b = bh >> 3, h = bh & 7;

        const float* base = proj + (size_t)b * T_ * PROJC + h * D_;
        const float* pfbase = base + (size_t)jjp * PROJC +
                              (isK1 ? C_ : 2 * C_) + d4p;

        // ---- init (item always; K2/V2 only on bh change) ----
        for (int idx = t; idx < 512; idx += 256) {
            int r = idx >> 6, d = idx & 63;
            Qs[idx]   = base[(size_t)(i0 + r) * PROJC + d] * QSC;
            accS[idx] = 0.f;
        }
        if (t < 32) redZ[t] = 0.f;
        if (bh != cur_bh) {
            for (int idx = t; idx < 192 * 32; idx += 256) {
                int k = idx >> 5, p = idx & 31;
                float2 v = *(const float2*)&base[(size_t)k * PROJC + 3 * C_ + 2 * p];
                K2h[k * 36 + p] = packh2(v.x, v.y);
            }
            for (int idx = t; idx < 96 * 64; idx += 256) {
                int pr = idx >> 6, d = idx & 63;
                float lo = base[(size_t)(2 * pr)     * PROJC + 4 * C_ + d];
                float hi = base[(size_t)(2 * pr + 1) * PROJC + 4 * C_ + d];
                V2h[pr * 72 + d] = packh2(lo, hi);
            }
            cur_bh = bh;
        }
        __syncthreads();

        // ---- pin Q fragments ----
        unsigned Qreg[32];
        #pragma unroll
        for (int rp = 0; rp < 4; rp++) {
            int i = (wm << 2) + rp;
            #pragma unroll
            for (int uq = 0; uq < 8; uq++) {
                int kk = uq >> 1;
                int d0 = (kk << 4) + (tid4 << 1) + ((uq & 1) << 3);
                Qreg[rp * 8 + uq] = packh2(Qs[(i << 6) + d0], Qs[(i << 6) + d0 + 1]);
            }
        }

        // ---- K1/V1 pipeline prologue for this run ----
        float4 preg = *(const float4*)(pfbase + (size_t)(jt0 << 3) * PROJC);
        if (isK1) {
            uint2 kw;
            kw.x = packh2(preg.x, preg.y);
            kw.y = packh2(preg.z, preg.w);
            *(uint2*)&K1h[jjp * 36 + (d4p >> 1)] = kw;
        } else {
            *(float4*)&V1s[(jjp << 6) + d4p] = preg;
        }
        if (run > 1)
            preg = *(const float4*)(pfbase + (size_t)((jt0 + 1) << 3) * PROJC);
        __syncthreads();

        for (int n_t = 0; n_t < run; n_t++) {
            const int buf = n_t & 1;
            const unsigned* K1b = K1h + buf * 288 + grp * 36;

            // ---- GEMM1 ----
            float c1[2][6][4] = {};
            #pragma unroll
            for (int kk = 0; kk < 4; kk++) {
                unsigned k1a  = K1b[(kk << 3) + tid4];
                unsigned k1b_ = K1b[(kk << 3) + 4 + tid4];
                unsigned A[2][4];
                #pragma unroll
                for (int a = 0; a < 2; a++) {
                    A[a][0] = hmul2u(Qreg[(a << 4) + (kk << 1)],     k1a);
                    A[a][1] = hmul2u(Qreg[(a << 4) + 8 + (kk << 1)], k1a);
                    A[a][2] = hmul2u(Qreg[(a << 4) + (kk << 1) + 1],     k1b_);
                    A[a][3] = hmul2u(Qreg[(a << 4) + 8 + (kk << 1) + 1], k1b_);
                }
                #pragma unroll
                for (int n = 0; n < 6; n++) {
                    int row = wn * 48 + (n << 3) + grp;
                    unsigned b0 = K2h[row * 36 + (kk << 3) + tid4];
                    unsigned b1 = K2h[row * 36 + (kk << 3) + 4 + tid4];
                    mma16816(c1[0][n], A[0], b0, b1);
                    mma16816(c1[1][n], A[1], b0, b1);
                }
            }

            // ---- fixed-max softmax ----
            unsigned ea[2][3][4];
            float zs[4] = {0.f, 0.f, 0.f, 0.f};
            #pragma unroll
            for (int a = 0; a < 2; a++)
                #pragma unroll
                for (int n = 0; n < 6; n++) {
                    float e0 = ex2(c1[a][n][0] - FMC);
                    float e1 = ex2(c1[a][n][1] - FMC);
                    float e2 = ex2(c1[a][n][2] - FMC);
                    float e3 = ex2(c1[a][n][3] - FMC);
                    zs[2*a+0] += e0 + e1;
                    zs[2*a+1] += e2 + e3;
                    unsigned p0 = packh2(e0, e1);
                    unsigned p1 = packh2(e2, e3);
                    if (n & 1) { ea[a][n >> 1][2] = p0; ea[a][n >> 1][3] = p1; }
                    else       { ea[a][n >> 1][0] = p0; ea[a][n >> 1][1] = p1; }
                }

            // ---- GEMM2 partial U ----
            #pragma unroll
            for (int nh = 0; nh < 2; nh++) {
                float uu[2][4][4] = {};
                #pragma unroll
                for (int kk2 = 0; kk2 < 3; kk2++) {
                    int rb = 24 * wn + (kk2 << 3);
                    #pragma unroll
                    for (int n = 0; n < 4; n++) {
                        int nn = (nh << 2) + n;
                        unsigned b0 = V2h[(rb + tid4) * 72 + (nn << 3) + grp];
                        unsigned b1 = V2h[(rb + 4 + tid4) * 72 + (nn << 3) + grp];
                        mma16816(uu[0][n], ea[0][kk2], b0, b1);
                        mma16816(uu[1][n], ea[1][kk2], b0, b1);
                    }
                }
                unsigned* Uq = Uh + wn * 2304;
                #pragma unroll
                for (int a = 0; a < 2; a++)
                    #pragma unroll
                    for (int n = 0; n < 4; n++) {
                        int nn = (nh << 2) + n;
                        int r  = (wm << 5) + (a << 4) + grp;
                        int cw = (nn << 2) + tid4;
                        Uq[r * 36 + cw]       = packh2(uu[a][n][0], uu[a][n][1]);
                        Uq[(r + 8) * 36 + cw] = packh2(uu[a][n][2], uu[a][n][3]);
                    }
            }

            // ---- commit K1/V1 for tile n_t+1; prefetch n_t+2 ----
            if (n_t + 1 < run) {
                if (isK1) {
                    uint2 kw;
                    kw.x = packh2(preg.x, preg.y);
                    kw.y = packh2(preg.z, preg.w);
                    *(uint2*)&K1h[(buf ^ 1) * 288 + jjp * 36 + (d4p >> 1)] = kw;
                } else {
                    *(float4*)&V1s[((buf ^ 1) << 9) + (jjp << 6) + d4p] = preg;
                }
                if (n_t + 2 < run)
                    preg = *(const float4*)(pfbase +
                            (size_t)((jt0 + n_t + 2) << 3) * PROJC);
            }
            __syncthreads();   // sync_B

            // ---- epilogue ----
            {
                #pragma unroll
                for (int s = 0; s < 4; s++)
                    #pragma unroll
                    for (int off = 16; off > 0; off >>= 1)
                        zs[s] += __shfl_xor_sync(0xffffffffu, zs[s], off);
                if (lane == 0) {
                    #pragma unroll
                    for (int s = 0; s < 4; s++)
                        redZ[(wn << 3) + (wm << 2) + s] += zs[s];
                }
                const int i = t >> 5;
                const float* V1b = V1s + (buf << 9);
                float2 acc = *(float2*)&accS[(i << 6) + (lane << 1)];
                #pragma unroll
                for (int jj = 0; jj < 8; jj++) {
                    int m = (i << 3) + jj;
                    float sx = 0.f, sy = 0.f;
                    #pragma unroll
                    for (int q = 0; q < 4; q++) {
                        unsigned uw = Uh[q * 2304 + m * 36 + lane];
                        float2 f = __half22float2(*(__half2*)&uw);
                        sx += f.x; sy += f.y;
                    }
                    float2 v1 = *(const float2*)&V1b[(jj << 6) + (lane << 1)];
                    acc.x += v1.x * sx;
                    acc.y += v1.y * sy;
                }
                *(float2*)&accS[(i << 6) + (lane << 1)] = acc;
            }
            __syncthreads();   // sync_E
        }

        // ---- finalize run: atomicAdd partials ----
        if (t < 8) {
            float Z = redZ[t] + redZ[8 + t] + redZ[16 + t] + redZ[24 + t];
            atomicAdd(&zp[(b * H_ + h) * T_ + i0 + t], Z);
        }
        {
            const int i = t >> 5;
            float2 acc = *(float2*)&accS[(i << 6) + (lane << 1)];
            float* dst = &accp[(size_t)(b * T_ + i0 + i) * C_ + h * D_ +
                               (lane << 1)];
            atomicAdd(dst,     acc.x);
            atomicAdd(dst + 1, acc.y);
        }
        __syncthreads();   // protect accS/redZ reuse by next run
        u += run;
    }
}

// ---------------------------------------------------------------------------
extern "C" void kernel_launch(void* const* d_in, const int* in_sizes, int n_in,
                              void* d_out, int out_size)
{
    const float* x     = (const float*)d_in[0];
    const float* W_in  = (const float*)d_in[1];
    const float* b_in  = (const float*)d_in[2];
    const float* W_out = (const float*)d_in[3];
    const float* b_out = (const float*)d_in[4];
    float* y = (float*)d_out;

    float *proj, *accp, *zvec;
    cudaGetSymbolAddress((void**)&proj, g_proj);
    cudaGetSymbolAddress((void**)&accp, g_accp);
    cudaGetSymbolAddress((void**)&zvec, g_z);

    const size_t SMEM = (size_t)SMEM_FLOATS * sizeof(float);   // 102,784 B
    cudaFuncSetAttribute(attn_kernel,
                         cudaFuncAttributeMaxDynamicSharedMemorySize, (int)SMEM);

    // 1) proj = x @ W_in + b_in (also zeroes accp/z)
    dim3 g1(PROJC / 64, (B_ * T_) / 64);
    gemm_h16_kernel<<<g1, 128>>>(x, W_in, b_in, proj, B_ * T_, PROJC, C_,
                                 nullptr, accp, zvec);

    // 2) fused attention: persistent CTAs, static j-tile-granular ranges
    attn_kernel<<<NCTA, 256, SMEM>>>(proj, accp, zvec);

    // 3) y = (accp / z) @ W_out + b_out (normalization fused into A-load)
    dim3 g2(C_ / 64, (B_ * T_) / 64);
    gemm_h16_kernel<<<g2, 128>>>(accp, W_out, b_out, y, B_ * T_, C_, C_,
                                 zvec, nullptr, nullptr);
}

// round 17
// speedup vs baseline: 1.0404x; 1.0111x over previous
#include <cuda_runtime.h>
#include <cuda_fp16.h>
#include <cstdint>

#define B_ 2
#define T_ 192
#define C_ 512
#define H_ 8
#define D_ 64
#define PROJC (5 * C_)  // 2560
#define NCTA 296
#define NU (16 * 24 * 24)       // 9216 units (bh x itile x jtile)
#define UBASE (NU / NCTA)       // 31
#define UREM  (NU % NCTA)       // 40

__device__ float g_proj[B_ * T_ * PROJC];
__device__ float g_accp[B_ * T_ * C_];
__device__ float g_z[B_ * H_ * T_];

// ---------------- helpers ----------------
__device__ __forceinline__ void mma16816(float* c, const unsigned* a,
                                         unsigned b0, unsigned b1) {
    asm volatile(
        "mma.sync.aligned.m16n8k16.row.col.f32.f16.f16.f32 "
        "{%0,%1,%2,%3},{%4,%5,%6,%7},{%8,%9},{%0,%1,%2,%3};\n"
        : "+f"(c[0]), "+f"(c[1]), "+f"(c[2]), "+f"(c[3])
        : "r"(a[0]), "r"(a[1]), "r"(a[2]), "r"(a[3]), "r"(b0), "r"(b1));
}
__device__ __forceinline__ unsigned packh2(float lo, float hi) {
    __half2 h = __floats2half2_rn(lo, hi);
    return *(unsigned*)&h;
}
__device__ __forceinline__ unsigned hmul2u(unsigned a, unsigned b) {
    __half2 r = __hmul2(*(__half2*)&a, *(__half2*)&b);
    return *(unsigned*)&r;
}
__device__ __forceinline__ float ex2(float x) {
    float r; asm("ex2.approx.ftz.f32 %0, %1;" : "=f"(r) : "f"(x)); return r;
}

// ---------------------------------------------------------------------------
// fp16 GEMM + bias (fp32 accum): 64x64 tile, 4 warps, K-step 32, double-buffer.
// zp   != null : scale A rows by 1/z (out-GEMM normalize)
// zacc != null : zero accp/z buffers first (proj prologue)
// ---------------------------------------------------------------------------
#define HA_STR 20
#define HB_STR 72
#define HAS (64 * HA_STR)
#define HBS (16 * HB_STR)
#define HSTG (HAS + HBS)

__global__ __launch_bounds__(128) void gemm_h16_kernel(
    const float* __restrict__ A, const float* __restrict__ Bm,
    const float* __restrict__ bias, float* __restrict__ C,
    int M, int N, int K,
    const float* __restrict__ zp, float* zacc, float* zz)
{
    __shared__ unsigned smh[2 * HSTG];

    const int t = threadIdx.x, lane = t & 31, w = t >> 5;
    const int grp = lane >> 2, tid4 = lane & 3;
    const int wm = w & 1, wn = w >> 1;
    const int row0 = blockIdx.y * 64, col0 = blockIdx.x * 64;

    if (zacc) {
        int gtid = (blockIdx.y * gridDim.x + blockIdx.x) * 128 + t;
        int nthr = gridDim.x * gridDim.y * 128;
        for (int idx = gtid; idx < B_ * T_ * C_; idx += nthr) zacc[idx] = 0.f;
        for (int idx = gtid; idx < B_ * H_ * T_; idx += nthr) zz[idx] = 0.f;
    }

    const int ar = t >> 1, acb = (t & 1) << 4;
    const int br = t >> 4, bc = (t & 15) << 2;

    float4 a0, a1, a2, a3, b0, b1, b2, b3;
    #define LDT(kt) do { \
        a0 = *(const float4*)&A[(size_t)(row0 + ar) * K + (kt) + acb]; \
        a1 = *(const float4*)&A[(size_t)(row0 + ar) * K + (kt) + acb + 4]; \
        a2 = *(const float4*)&A[(size_t)(row0 + ar) * K + (kt) + acb + 8]; \
        a3 = *(const float4*)&A[(size_t)(row0 + ar) * K + (kt) + acb + 12]; \
        if (zp) { \
            int rr = row0 + ar; int bb = rr / T_, tt = rr - bb * T_; \
            int hh = ((kt) + acb) >> 6; \
            float zi = 1.0f / zp[(bb * H_ + hh) * T_ + tt]; \
            a0.x *= zi; a0.y *= zi; a0.z *= zi; a0.w *= zi; \
            a1.x *= zi; a1.y *= zi; a1.z *= zi; a1.w *= zi; \
            a2.x *= zi; a2.y *= zi; a2.z *= zi; a2.w *= zi; \
            a3.x *= zi; a3.y *= zi; a3.z *= zi; a3.w *= zi; \
        } \
        b0 = *(const float4*)&Bm[(size_t)((kt) + 2 * br)      * N + col0 + bc]; \
        b1 = *(const float4*)&Bm[(size_t)((kt) + 2 * br + 1)  * N + col0 + bc]; \
        b2 = *(const float4*)&Bm[(size_t)((kt) + 2 * br + 16) * N + col0 + bc]; \
        b3 = *(const float4*)&Bm[(size_t)((kt) + 2 * br + 17) * N + col0 + bc]; \
    } while (0)
    #define STT(S) do { \
        unsigned* Ah = (S); unsigned* Bh = (S) + HAS; \
        int aw = ar * HA_STR + (acb >> 1); \
        Ah[aw + 0] = packh2(a0.x, a0.y); Ah[aw + 1] = packh2(a0.z, a0.w); \
        Ah[aw + 2] = packh2(a1.x, a1.y); Ah[aw + 3] = packh2(a1.z, a1.w); \
        Ah[aw + 4] = packh2(a2.x, a2.y); Ah[aw + 5] = packh2(a2.z, a2.w); \
        Ah[aw + 6] = packh2(a3.x, a3.y); Ah[aw + 7] = packh2(a3.z, a3.w); \
        int bw = br * HB_STR + bc; \
        Bh[bw + 0] = packh2(b0.x, b1.x); Bh[bw + 1] = packh2(b0.y, b1.y); \
        Bh[bw + 2] = packh2(b0.z, b1.z); Bh[bw + 3] = packh2(b0.w, b1.w); \
        int bw2 = (br + 8) * HB_STR + bc; \
        Bh[bw2 + 0] = packh2(b2.x, b3.x); Bh[bw2 + 1] = packh2(b2.y, b3.y); \
        Bh[bw2 + 2] = packh2(b2.z, b3.z); Bh[bw2 + 3] = packh2(b2.w, b3.w); \
    } while (0)

    const int niter = K >> 5;
    LDT(0);
    STT(smh);
    if (niter > 1) LDT(32);
    __syncthreads();

    float c[2][4][4] = {};

    for (int it = 0; it < niter; it++) {
        unsigned* S = smh + (it & 1) * HSTG;
        unsigned* Ah = S;
        unsigned* Bh = S + HAS;

        #pragma unroll
        for (int kc = 0; kc < 2; kc++) {
            const int k8 = kc << 3;
            unsigned a[2][4];
            #pragma unroll
            for (int mt = 0; mt < 2; mt++) {
                int r = (wm << 5) + (mt << 4) + grp;
                a[mt][0] = Ah[r * HA_STR + k8 + tid4];
                a[mt][1] = Ah[(r + 8) * HA_STR + k8 + tid4];
                a[mt][2] = Ah[r * HA_STR + k8 + 4 + tid4];
                a[mt][3] = Ah[(r + 8) * HA_STR + k8 + 4 + tid4];
            }
            #pragma unroll
            for (int n = 0; n < 4; n++) {
                int cc = (wn << 5) + (n << 3) + grp;
                unsigned bb0 = Bh[(k8 + tid4) * HB_STR + cc];
                unsigned bb1 = Bh[(k8 + 4 + tid4) * HB_STR + cc];
                mma16816(c[0][n], a[0], bb0, bb1);
                mma16816(c[1][n], a[1], bb0, bb1);
            }
        }

        if (it + 1 < niter) {
            unsigned* Sn = smh + ((it + 1) & 1) * HSTG;
            STT(Sn);
            if (it + 2 < niter) LDT((it + 2) << 5);
            __syncthreads();
        }
    }

    #pragma unroll
    for (int mt = 0; mt < 2; mt++)
        #pragma unroll
        for (int n = 0; n < 4; n++) {
            int row = row0 + (wm << 5) + (mt << 4) + grp;
            int col = col0 + (wn << 5) + (n << 3) + (tid4 << 1);
            float2 bv = *(const float2*)&bias[col];
            *(float2*)&C[(size_t)row * N + col] =
                make_float2(c[mt][n][0] + bv.x, c[mt][n][1] + bv.y);
            *(float2*)&C[(size_t)(row + 8) * N + col] =
                make_float2(c[mt][n][2] + bv.x, c[mt][n][3] + bv.y);
        }
    #undef LDT
    #undef STT
}

// ---------------------------------------------------------------------------
// Fused two-simplicial attention: persistent CTAs with static contiguous
// unit ranges. Per tile: [epilogue(n-1) || GEMM1(n)] -> BAR_A -> softmax ->
// GEMM2 -> commit -> BAR_B. acc lives in registers.
// ---------------------------------------------------------------------------
#define QSC 0.18033688011112042f
#define FMC 5.770780163555854f

#define OFF_Q    0
#define OFF_V1   512
#define OFF_RZ   1536
#define OFF_K1H  1568
#define OFF_K2H  2144
#define OFF_V2H  9056
#define OFF_UH   15968
#define SMEM_FLOATS 25184  // 100,736 B

__global__ __launch_bounds__(256, 2) void attn_kernel(
    const float* __restrict__ proj, float* __restrict__ accp,
    float* __restrict__ zp)
{
    extern __shared__ float sm[];
    float* Qs   = sm + OFF_Q;
    float* V1s  = sm + OFF_V1;
    float* redZ = sm + OFF_RZ;
    unsigned* K1h = (unsigned*)(sm + OFF_K1H);
    unsigned* K2h = (unsigned*)(sm + OFF_K2H);
    unsigned* V2h = (unsigned*)(sm + OFF_V2H);
    unsigned* Uh  = (unsigned*)(sm + OFF_UH);

    const int t = threadIdx.x, lane = t & 31, w = t >> 5;
    const int grp = lane >> 2, tid4 = lane & 3;
    const int wm = w & 1;
    const int wn = w >> 1;

    const int ttp = t & 127;
    const int jjp = ttp >> 4;
    const int d4p = (ttp & 15) << 2;
    const bool isK1 = (t < 128);

    const int cid = blockIdx.x;
    int u   = UBASE * cid + (cid < UREM ? cid : UREM);
    int end = u + UBASE + (cid < UREM ? 1 : 0);

    int cur_bh = -1;
    const int ei = t >> 5;           // epilogue row i for this thread
    const int ed = lane << 1;        // epilogue d-pair

    while (u < end) {
        const int item = u / 24;
        const int jt0  = u - item * 24;
        const int bh   = item / 24;
        const int i0   = (item - bh * 24) << 3;
        const int run  = min(24 - jt0, end - u);
        const int b = bh >> 3, h = bh & 7;

        const float* base = proj + (size_t)b * T_ * PROJC + h * D_;
        const float* pfbase = base + (size_t)jjp * PROJC +
                              (isK1 ? C_ : 2 * C_) + d4p;

        // ---- init (item always; K2/V2 only on bh change) ----
        for (int idx = t; idx < 512; idx += 256) {
            int r = idx >> 6, d = idx & 63;
            Qs[idx] = base[(size_t)(i0 + r) * PROJC + d] * QSC;
        }
        if (t < 32) redZ[t] = 0.f;
        if (bh != cur_bh) {
            for (int idx = t; idx < 192 * 32; idx += 256) {
                int k = idx >> 5, p = idx & 31;
                float2 v = *(const float2*)&base[(size_t)k * PROJC + 3 * C_ + 2 * p];
                K2h[k * 36 + p] = packh2(v.x, v.y);
            }
            for (int idx = t; idx < 96 * 64; idx += 256) {
                int pr = idx >> 6, d = idx & 63;
                float lo = base[(size_t)(2 * pr)     * PROJC + 4 * C_ + d];
                float hi = base[(size_t)(2 * pr + 1) * PROJC + 4 * C_ + d];
                V2h[pr * 72 + d] = packh2(lo, hi);
            }
            cur_bh = bh;
        }
        __syncthreads();

        // ---- pin Q fragments ----
        unsigned Qreg[32];
        #pragma unroll
        for (int rp = 0; rp < 4; rp++) {
            int i = (wm << 2) + rp;
            #pragma unroll
            for (int uq = 0; uq < 8; uq++) {
                int kk = uq >> 1;
                int d0 = (kk << 4) + (tid4 << 1) + ((uq & 1) << 3);
                Qreg[rp * 8 + uq] = packh2(Qs[(i << 6) + d0], Qs[(i << 6) + d0 + 1]);
            }
        }

        // ---- K1/V1 pipeline prologue for this run ----
        float4 preg = *(const float4*)(pfbase + (size_t)(jt0 << 3) * PROJC);
        if (isK1) {
            uint2 kw;
            kw.x = packh2(preg.x, preg.y);
            kw.y = packh2(preg.z, preg.w);
            *(uint2*)&K1h[jjp * 36 + (d4p >> 1)] = kw;
        } else {
            *(float4*)&V1s[(jjp << 6) + d4p] = preg;
        }
        if (run > 1)
            preg = *(const float4*)(pfbase + (size_t)((jt0 + 1) << 3) * PROJC);
        __syncthreads();

        float accx = 0.f, accy = 0.f;   // register accumulator

        for (int n_t = 0; n_t < run; n_t++) {
            const int buf = n_t & 1;
            const unsigned* K1b = K1h + buf * 288 + grp * 36;

            // ---- GEMM1(n) [tensor pipe] ----
            float c1[2][6][4] = {};
            #pragma unroll
            for (int kk = 0; kk < 4; kk++) {
                unsigned k1a  = K1b[(kk << 3) + tid4];
                unsigned k1b_ = K1b[(kk << 3) + 4 + tid4];
                unsigned A[2][4];
                #pragma unroll
                for (int a = 0; a < 2; a++) {
                    A[a][0] = hmul2u(Qreg[(a << 4) + (kk << 1)],     k1a);
                    A[a][1] = hmul2u(Qreg[(a << 4) + 8 + (kk << 1)], k1a);
                    A[a][2] = hmul2u(Qreg[(a << 4) + (kk << 1) + 1],     k1b_);
                    A[a][3] = hmul2u(Qreg[(a << 4) + 8 + (kk << 1) + 1], k1b_);
                }
                #pragma unroll
                for (int n = 0; n < 6; n++) {
                    int row = wn * 48 + (n << 3) + grp;
                    unsigned b0 = K2h[row * 36 + (kk << 3) + tid4];
                    unsigned b1 = K2h[row * 36 + (kk << 3) + 4 + tid4];
                    mma16816(c1[0][n], A[0], b0, b1);
                    mma16816(c1[1][n], A[1], b0, b1);
                }
            }

            // ---- epilogue(n-1) [LSU/FFMA; overlaps GEMM1 issue] ----
            if (n_t > 0) {
                const float* V1b = V1s + (((n_t - 1) & 1) << 9);
                #pragma unroll
                for (int jj = 0; jj < 8; jj++) {
                    int m = (ei << 3) + jj;
                    float sx = 0.f, sy = 0.f;
                    #pragma unroll
                    for (int q = 0; q < 4; q++) {
                        unsigned uw = Uh[q * 2304 + m * 36 + lane];
                        float2 f = __half22float2(*(__half2*)&uw);
                        sx += f.x; sy += f.y;
                    }
                    float2 v1 = *(const float2*)&V1b[(jj << 6) + ed];
                    accx += v1.x * sx;
                    accy += v1.y * sy;
                }
            }
            __syncthreads();   // BAR_A: epi reads done; Uh/V1 writable

            // ---- fixed-max softmax(n) ----
            unsigned ea[2][3][4];
            float zs[4] = {0.f, 0.f, 0.f, 0.f};
            #pragma unroll
            for (int a = 0; a < 2; a++)
                #pragma unroll
                for (int n = 0; n < 6; n++) {
                    float e0 = ex2(c1[a][n][0] - FMC);
                    float e1 = ex2(c1[a][n][1] - FMC);
                    float e2 = ex2(c1[a][n][2] - FMC);
                    float e3 = ex2(c1[a][n][3] - FMC);
                    zs[2*a+0] += e0 + e1;
                    zs[2*a+1] += e2 + e3;
                    unsigned p0 = packh2(e0, e1);
                    unsigned p1 = packh2(e2, e3);
                    if (n & 1) { ea[a][n >> 1][2] = p0; ea[a][n >> 1][3] = p1; }
                    else       { ea[a][n >> 1][0] = p0; ea[a][n >> 1][1] = p1; }
                }
            #pragma unroll
            for (int s = 0; s < 4; s++)
                #pragma unroll
                for (int off = 16; off > 0; off >>= 1)
                    zs[s] += __shfl_xor_sync(0xffffffffu, zs[s], off);
            if (lane == 0) {
                #pragma unroll
                for (int s = 0; s < 4; s++)
                    redZ[(wn << 3) + (wm << 2) + s] += zs[s];
            }

            // ---- GEMM2(n): partial U -> Uh ----
            #pragma unroll
            for (int nh = 0; nh < 2; nh++) {
                float uu[2][4][4] = {};
                #pragma unroll
                for (int kk2 = 0; kk2 < 3; kk2++) {
                    int rb = 24 * wn + (kk2 << 3);
                    #pragma unroll
                    for (int n = 0; n < 4; n++) {
                        int nn = (nh << 2) + n;
                        unsigned b0 = V2h[(rb + tid4) * 72 + (nn << 3) + grp];
                        unsigned b1 = V2h[(rb + 4 + tid4) * 72 + (nn << 3) + grp];
                        mma16816(uu[0][n], ea[0][kk2], b0, b1);
                        mma16816(uu[1][n], ea[1][kk2], b0, b1);
                    }
                }
                unsigned* Uq = Uh + wn * 2304;
                #pragma unroll
                for (int a = 0; a < 2; a++)
                    #pragma unroll
                    for (int n = 0; n < 4; n++) {
                        int nn = (nh << 2) + n;
                        int r  = (wm << 5) + (a << 4) + grp;
                        int cw = (nn << 2) + tid4;
                        Uq[r * 36 + cw]       = packh2(uu[a][n][0], uu[a][n][1]);
                        Uq[(r + 8) * 36 + cw] = packh2(uu[a][n][2], uu[a][n][3]);
                    }
            }

            // ---- commit K1/V1 for tile n_t+1; prefetch n_t+2 ----
            if (n_t + 1 < run) {
                if (isK1) {
                    uint2 kw;
                    kw.x = packh2(preg.x, preg.y);
                    kw.y = packh2(preg.z, preg.w);
                    *(uint2*)&K1h[(buf ^ 1) * 288 + jjp * 36 + (d4p >> 1)] = kw;
                } else {
                    *(float4*)&V1s[((buf ^ 1) << 9) + (jjp << 6) + d4p] = preg;
                }
                if (n_t + 2 < run)
                    preg = *(const float4*)(pfbase +
                            (size_t)((jt0 + n_t + 2) << 3) * PROJC);
            }
            __syncthreads();   // BAR_B: Uh + next K1/V1 visible
        }

        // ---- final epilogue for tile run-1 ----
        {
            const float* V1b = V1s + (((run - 1) & 1) << 9);
            #pragma unroll
            for (int jj = 0; jj < 8; jj++) {
                int m = (ei << 3) + jj;
                float sx = 0.f, sy = 0.f;
                #pragma unroll
                for (int q = 0; q < 4; q++) {
                    unsigned uw = Uh[q * 2304 + m * 36 + lane];
                    float2 f = __half22float2(*(__half2*)&uw);
                    sx += f.x; sy += f.y;
                }
                float2 v1 = *(const float2*)&V1b[(jj << 6) + ed];
                accx += v1.x * sx;
                accy += v1.y * sy;
            }
        }

        // ---- finalize run: atomicAdd partials ----
        if (t < 8) {
            float Z = redZ[t] + redZ[8 + t] + redZ[16 + t] + redZ[24 + t];
            atomicAdd(&zp[(b * H_ + h) * T_ + i0 + t], Z);
        }
        {
            float* dst = &accp[(size_t)(b * T_ + i0 + ei) * C_ + h * D_ + ed];
            atomicAdd(dst,     accx);
            atomicAdd(dst + 1, accy);
        }
        __syncthreads();   // protect redZ/Uh reuse by next run
        u += run;
    }
}

// ---------------------------------------------------------------------------
extern "C" void kernel_launch(void* const* d_in, const int* in_sizes, int n_in,
                              void* d_out, int out_size)
{
    const float* x     = (const float*)d_in[0];
    const float* W_in  = (const float*)d_in[1];
    const float* b_in  = (const float*)d_in[2];
    const float* W_out = (const float*)d_in[3];
    const float* b_out = (const float*)d_in[4];
    float* y = (float*)d_out;

    float *proj, *accp, *zvec;
    cudaGetSymbolAddress((void**)&proj, g_proj);
    cudaGetSymbolAddress((void**)&accp, g_accp);
    cudaGetSymbolAddress((void**)&zvec, g_z);

    const size_t SMEM = (size_t)SMEM_FLOATS * sizeof(float);   // 100,736 B
    cudaFuncSetAttribute(attn_kernel,
                         cudaFuncAttributeMaxDynamicSharedMemorySize, (int)SMEM);

    // 1) proj = x @ W_in + b_in (also zeroes accp/z)
    dim3 g1(PROJC / 64, (B_ * T_) / 64);
    gemm_h16_kernel<<<g1, 128>>>(x, W_in, b_in, proj, B_ * T_, PROJC, C_,
                                 nullptr, accp, zvec);

    // 2) fused attention: persistent CTAs, j-tile-granular static ranges
    attn_kernel<<<NCTA, 256, SMEM>>>(proj, accp, zvec);

    // 3) y = (accp / z) @ W_out + b_out (normalization fused into A-load)
    dim3 g2(C_ / 64, (B_ * T_) / 64);
    gemm_h16_kernel<<<g2, 128>>>(accp, W_out, b_out, y, B_ * T_, C_, C_,
                                 zvec, nullptr, nullptr);
}